// round 7
// baseline (speedup 1.0000x reference)
#include <cuda_runtime.h>
#include <cuda_bf16.h>
#include <math.h>
#include <stdint.h>

// Problem constants (ContTimeLSTM_66623532695635)
#define Bsz 128
#define Lseq 512
#define Iin 256
#define Dh 512
#define ND 3584          // 7*D
#define FIN 768          // I + D
#define BD (Bsz*Dh)      // 65536

#define GRID_R 128       // persistent recur blocks
#define NTR 256          // 8 warps: wm = w&1 (m32 group), wk = w>>1 (k quarter)

// ---------------- device scratch ----------------
__device__ float g_xp[(size_t)Lseq * Bsz * ND];        // ~940 MB, [t][b][n]
__device__ uint32_t g_Hsplit[2][BD];                   // packed bf16 (hi | lo<<16)
__device__ uint32_t g_xpack[(size_t)Bsz * Lseq * Iin]; // packed masked x
#define WFRAG_PLANE (28 * 16384)
__device__ uint32_t g_wfrag[2 * WFRAG_PLANE];          // W x-part fragments
__device__ float g_proj0[ND];
__device__ __align__(256) unsigned g_bar2[64];         // [0]: half 0, [32]: half 1 (128B apart)

__device__ __forceinline__ float sigf(float x) { return 1.0f / (1.0f + expf(-x)); }
__device__ __forceinline__ float softplusf(float x) {
    return (x > 0.0f) ? (x + log1pf(expf(-x))) : log1pf(expf(x));
}
__device__ __forceinline__ unsigned ld_acq(unsigned* p) {
    unsigned v;
    asm volatile("ld.acquire.gpu.u32 %0, [%1];" : "=r"(v) : "l"(p) : "memory");
    return v;
}
__device__ __forceinline__ void red_rel_add1(unsigned* p) {
    asm volatile("red.release.gpu.global.add.u32 [%0], 1;" :: "l"(p) : "memory");
}
__device__ __forceinline__ uint32_t prmt_(uint32_t a, uint32_t b, uint32_t s) {
    uint32_t r;
    asm("prmt.b32 %0, %1, %2, %3;" : "=r"(r) : "r"(a), "r"(b), "r"(s));
    return r;
}
__device__ __forceinline__ uint32_t pack_hl(float v) {
    __nv_bfloat16 hi = __float2bfloat16(v);
    __nv_bfloat16 lo = __float2bfloat16(v - __bfloat162float(hi));
    return ((uint32_t)__bfloat16_as_ushort(lo) << 16) | __bfloat16_as_ushort(hi);
}
__device__ __forceinline__ uint32_t pack2bf(__nv_bfloat16 a, __nv_bfloat16 b) {
    return ((uint32_t)__bfloat16_as_ushort(b) << 16) | __bfloat16_as_ushort(a);
}

#define MMA_BF16(d, a, b0, b1) \
    asm volatile("mma.sync.aligned.m16n8k16.row.col.f32.bf16.bf16.f32 " \
        "{%0,%1,%2,%3}, {%4,%5,%6,%7}, {%8,%9}, {%0,%1,%2,%3};" \
        : "+f"((d)[0]), "+f"((d)[1]), "+f"((d)[2]), "+f"((d)[3]) \
        : "r"((a)[0]), "r"((a)[1]), "r"((a)[2]), "r"((a)[3]), "r"(b0), "r"(b1))

// ---------------- launch 1: reset barriers + proj0 ----------------
__global__ void prep_kernel(const float* __restrict__ bos,
                            const float* __restrict__ W,
                            const float* __restrict__ bias) {
    int n = blockIdx.x * blockDim.x + threadIdx.x;
    if (n == 0) { g_bar2[0] = 0u; g_bar2[32] = 0u; }
    if (n >= ND) return;
    const float* wrow = W + (size_t)n * FIN;
    float acc = bias[n];
    #pragma unroll 8
    for (int i = 0; i < Iin; i++) acc += bos[i] * wrow[i];
    g_proj0[n] = acc;
}

// ---------------- launch 2: pack x (masked) + W x-part fragments ----------------
#define XN (Bsz * Lseq * Iin)          // 16,777,216
#define WN (28 * 16 * 16 * 32)         // 229,376
__global__ void pack_kernel(const float* __restrict__ x,
                            const int* __restrict__ sl,
                            const float* __restrict__ W) {
    int idx = blockIdx.x * blockDim.x + threadIdx.x;
    if (idx < XN) {
        int row = idx >> 8;
        int i = idx & 255;
        int t = row >> 7;
        int b = row & 127;
        float v = (t < __ldg(sl + b)) ? x[((size_t)b * Lseq + t) * Iin + i] : 0.0f;
        g_xpack[idx] = pack_hl(v);
        return;
    }
    int e = idx - XN;
    if (e >= WN) return;
    int lane = e & 31;
    int nt = (e >> 5) & 15;
    int ks = (e >> 9) & 15;
    int nb = e >> 13;
    int gg = lane >> 2, tt = lane & 3;
    int n = nb * 128 + nt * 8 + gg;
    const float* wr = W + (size_t)n * FIN + ks * 16 + tt * 2;
    float w0 = wr[0], w1 = wr[1], w2 = wr[8], w3 = wr[9];
    __nv_bfloat16 h0 = __float2bfloat16(w0), h1 = __float2bfloat16(w1);
    __nv_bfloat16 h2 = __float2bfloat16(w2), h3 = __float2bfloat16(w3);
    __nv_bfloat16 l0 = __float2bfloat16(w0 - __bfloat162float(h0));
    __nv_bfloat16 l1 = __float2bfloat16(w1 - __bfloat162float(h1));
    __nv_bfloat16 l2 = __float2bfloat16(w2 - __bfloat162float(h2));
    __nv_bfloat16 l3 = __float2bfloat16(w3 - __bfloat162float(h3));
    size_t base = (size_t)e * 2;
    g_wfrag[base] = pack2bf(h0, h1);
    g_wfrag[base + 1] = pack2bf(h2, h3);
    g_wfrag[WFRAG_PLANE + base] = pack2bf(l0, l1);
    g_wfrag[WFRAG_PLANE + base + 1] = pack2bf(l2, l3);
}

// ---------------- launch 3: XP = mask(x) @ Wx^T + bias via HMMA ----------------
__global__ __launch_bounds__(256, 1)
void xproj_hmma_kernel(const float* __restrict__ bias) {
    extern __shared__ uint32_t sW[];   // 32768 u32
    const int tid = threadIdx.x;
    const int w = tid >> 5, lane = tid & 31;
    const int g = lane >> 2, tq = lane & 3;
    const int nb = blockIdx.x, mb = blockIdx.y;

    #pragma unroll
    for (int p = 0; p < 2; p++) {
        const uint4* src = (const uint4*)(g_wfrag + (size_t)p * WFRAG_PLANE + nb * 16384);
        uint4* dst = (uint4*)(sW + p * 16384);
        #pragma unroll
        for (int i = 0; i < 16; i++) dst[tid + i * 256] = src[tid + i * 256];
    }
    __syncthreads();

    const int r0 = mb * 128 + w * 16 + g;

    float acc[16][4];
    #pragma unroll
    for (int nt = 0; nt < 16; nt++) {
        int n = nb * 128 + nt * 8 + tq * 2;
        float b0 = __ldg(bias + n), b1 = __ldg(bias + n + 1);
        acc[nt][0] = b0; acc[nt][1] = b1; acc[nt][2] = b0; acc[nt][3] = b1;
    }

    uint2 ring[2][4];
    #pragma unroll
    for (int p = 0; p < 2; p++) {
        int kb = p * 16 + tq * 2;
        ring[p][0] = *(const uint2*)(g_xpack + (size_t)r0 * Iin + kb);
        ring[p][1] = *(const uint2*)(g_xpack + (size_t)(r0 + 8) * Iin + kb);
        ring[p][2] = *(const uint2*)(g_xpack + (size_t)r0 * Iin + kb + 8);
        ring[p][3] = *(const uint2*)(g_xpack + (size_t)(r0 + 8) * Iin + kb + 8);
    }

    #pragma unroll 2
    for (int ks = 0; ks < 16; ks++) {
        int slot = ks & 1;
        uint32_t ah[4], al[4];
        #pragma unroll
        for (int q = 0; q < 4; q++) {
            ah[q] = prmt_(ring[slot][q].x, ring[slot][q].y, 0x5410);
            al[q] = prmt_(ring[slot][q].x, ring[slot][q].y, 0x7632);
        }
        if (ks + 2 < 16) {
            int kb = (ks + 2) * 16 + tq * 2;
            ring[slot][0] = *(const uint2*)(g_xpack + (size_t)r0 * Iin + kb);
            ring[slot][1] = *(const uint2*)(g_xpack + (size_t)(r0 + 8) * Iin + kb);
            ring[slot][2] = *(const uint2*)(g_xpack + (size_t)r0 * Iin + kb + 8);
            ring[slot][3] = *(const uint2*)(g_xpack + (size_t)(r0 + 8) * Iin + kb + 8);
        }
        uint32_t bhx[16][2];
        #pragma unroll
        for (int nt = 0; nt < 16; nt++) {
            uint2 vh = *(const uint2*)(sW + ((ks * 16 + nt) * 32 + lane) * 2);
            bhx[nt][0] = vh.x; bhx[nt][1] = vh.y;
            MMA_BF16(acc[nt], ah, vh.x, vh.y);
        }
        #pragma unroll
        for (int nt = 0; nt < 16; nt++)
            MMA_BF16(acc[nt], al, bhx[nt][0], bhx[nt][1]);
        #pragma unroll
        for (int nt = 0; nt < 16; nt++) {
            uint2 vl = *(const uint2*)(sW + 16384 + ((ks * 16 + nt) * 32 + lane) * 2);
            MMA_BF16(acc[nt], ah, vl.x, vl.y);
        }
    }

    #pragma unroll
    for (int nt = 0; nt < 16; nt++) {
        int n = nb * 128 + nt * 8 + tq * 2;
        *(float2*)&g_xp[(size_t)r0 * ND + n] = make_float2(acc[nt][0], acc[nt][1]);
        *(float2*)&g_xp[(size_t)(r0 + 8) * ND + n] = make_float2(acc[nt][2], acc[nt][3]);
    }
}

// ================= launch 4: persistent recurrence =================
// 128 blocks = 64 d-chunks x 2 batch-halves. 8 warps = 2 wm (m32) x 4 wk (K=128).
// Per-half grid barrier; tid0-only poll. Split-K reduce in smem (stride 60 floats).
#define NFRAG 224                    // 32 ks * 7 nt
#define SB_U32 (NFRAG * 32 * 4)      // 28672 u32 = 114688 B
#define RED_STRIDE 60                // floats per (wk,wm,lane) slot
#define SRED_FLOATS (3 * 64 * RED_STRIDE)
#define SMEM_RECUR (SB_U32 * 4 + SRED_FLOATS * 4)

__global__ __launch_bounds__(NTR, 1)
void recur_kernel(const float* __restrict__ W,
                  const float* __restrict__ dt,
                  const int* __restrict__ sl,
                  float* __restrict__ out_h,
                  float* __restrict__ out_final) {
    extern __shared__ uint32_t sB[];
    float* sRed = (float*)(sB + SB_U32);

    const int tid = threadIdx.x;
    const int w = tid >> 5;
    const int lane = tid & 31;
    const int g = lane >> 2;
    const int tq = lane & 3;
    const int wm = w & 1;            // m32 group
    const int wk = w >> 1;           // k quarter (0..3)
    const int dn = blockIdx.x >> 1;
    const int bh = blockIdx.x & 1;
    const int d0 = dn * 8 + tq * 2;
    unsigned* barp = &g_bar2[bh * 32];

    // ---- pack W h-part fragments (interleaved hi/lo) ----
    for (int e = tid; e < NFRAG * 32; e += NTR) {
        int f = e >> 5;
        int l = e & 31;
        int ks = f / 7, nt = f % 7;
        int gg = l >> 2, tt = l & 3;
        int n = nt * Dh + dn * 8 + gg;
        const float* wr = W + (size_t)n * FIN + Iin + ks * 16;
        float w0 = wr[tt * 2], w1 = wr[tt * 2 + 1];
        float w2 = wr[tt * 2 + 8], w3 = wr[tt * 2 + 9];
        __nv_bfloat16 h0 = __float2bfloat16(w0), h1 = __float2bfloat16(w1);
        __nv_bfloat16 h2 = __float2bfloat16(w2), h3 = __float2bfloat16(w3);
        __nv_bfloat16 l0 = __float2bfloat16(w0 - __bfloat162float(h0));
        __nv_bfloat16 l1 = __float2bfloat16(w1 - __bfloat162float(h1));
        __nv_bfloat16 l2 = __float2bfloat16(w2 - __bfloat162float(h2));
        __nv_bfloat16 l3 = __float2bfloat16(w3 - __bfloat162float(h3));
        uint32_t* p = sB + (size_t)e * 4;
        p[0] = pack2bf(h0, h1);
        p[1] = pack2bf(h2, h3);
        p[2] = pack2bf(l0, l1);
        p[3] = pack2bf(l2, l3);
    }

    // rows: [mt][rh] = bh*64 + wm*32 + mt*16 + rh*8 + g
    int rows4[2][2];
    #pragma unroll
    for (int mt = 0; mt < 2; mt++)
        #pragma unroll
        for (int rh = 0; rh < 2; rh++)
            rows4[mt][rh] = bh * 64 + wm * 32 + mt * 16 + rh * 8 + g;

    int lenr[2][2] = {{0, 0}, {0, 0}};
    float stC[2][2][2], stCe[2][2][2];

    if (wk == 0) {
        #pragma unroll
        for (int mt = 0; mt < 2; mt++)
            #pragma unroll
            for (int rh = 0; rh < 2; rh++) {
                int b = rows4[mt][rh];
                lenr[mt][rh] = sl[b];
                float dtv = dt[b * Lseq + 0];
                float h2v[2];
                uint32_t hp[2];
                #pragma unroll
                for (int cj = 0; cj < 2; cj++) {
                    int d = d0 + cj;
                    float p0 = g_proj0[0 * Dh + d];
                    float p2 = g_proj0[2 * Dh + d];
                    float p4 = g_proj0[4 * Dh + d];
                    float p5 = g_proj0[5 * Dh + d];
                    float p6 = g_proj0[6 * Dh + d];
                    float z   = tanhf(p5);
                    float cs0 = sigf(p0) * z;
                    float ce0 = sigf(p2) * z;
                    float o0  = sigf(p4);
                    float dn0 = softplusf(p6);
                    float c = ce0 + (cs0 - ce0) * expf(-dn0 * dtv);
                    float h = o0 * tanhf(c);
                    stC[mt][rh][cj] = c;
                    stCe[mt][rh][cj] = ce0;
                    h2v[cj] = h;
                    hp[cj] = pack_hl(h);
                }
                *(float2*)&out_h[((size_t)b * Lseq + 0) * Dh + d0] = make_float2(h2v[0], h2v[1]);
                *(uint2*)&g_Hsplit[0][b * Dh + d0] = make_uint2(hp[0], hp[1]);
            }
    }

    // acc: wk0 = XP[0], others zero
    float acc[2][7][4];
    if (wk == 0) {
        #pragma unroll
        for (int mt = 0; mt < 2; mt++)
            #pragma unroll
            for (int nt = 0; nt < 7; nt++) {
                float2 x0 = *(const float2*)(g_xp + (size_t)rows4[mt][0] * ND + nt * Dh + d0);
                float2 x1 = *(const float2*)(g_xp + (size_t)rows4[mt][1] * ND + nt * Dh + d0);
                acc[mt][nt][0] = x0.x; acc[mt][nt][1] = x0.y;
                acc[mt][nt][2] = x1.x; acc[mt][nt][3] = x1.y;
            }
    } else {
        #pragma unroll
        for (int mt = 0; mt < 2; mt++)
            #pragma unroll
            for (int nt = 0; nt < 7; nt++)
                #pragma unroll
                for (int ci = 0; ci < 4; ci++) acc[mt][nt][ci] = 0.0f;
    }

    __syncthreads();                         // sB + h0 stores ordered (cta fence)
    if (wk == 0 && lane == 0) red_rel_add1(barp);   // 2 arrivals/block -> 128/half

    unsigned tgt = 128;
    if (tid == 0) { while (ld_acq(barp) < tgt) {} }
    __syncthreads();

    const int kbase = wk * 128;              // u32 (d) offset of this k-quarter

    for (int t = 0; t < Lseq; t++) {
        const uint32_t* Hs = g_Hsplit[t & 1];

        // ring-2 A prefetch: 8 uint2 per slot (2 mt x {r0 kb, r1 kb, r0 kb+8, r1 kb+8})
        uint2 ring[2][8];
        #pragma unroll
        for (int p = 0; p < 2; p++) {
            int kb = kbase + p * 16 + tq * 2;
            #pragma unroll
            for (int mt = 0; mt < 2; mt++) {
                ring[p][mt * 4 + 0] = *(const uint2*)(Hs + rows4[mt][0] * Dh + kb);
                ring[p][mt * 4 + 1] = *(const uint2*)(Hs + rows4[mt][1] * Dh + kb);
                ring[p][mt * 4 + 2] = *(const uint2*)(Hs + rows4[mt][0] * Dh + kb + 8);
                ring[p][mt * 4 + 3] = *(const uint2*)(Hs + rows4[mt][1] * Dh + kb + 8);
            }
        }

        #pragma unroll 2
        for (int ks = 0; ks < 8; ks++) {
            int slot = ks & 1;
            uint32_t ah[2][4], al[2][4];
            #pragma unroll
            for (int mt = 0; mt < 2; mt++)
                #pragma unroll
                for (int q = 0; q < 4; q++) {
                    ah[mt][q] = prmt_(ring[slot][mt * 4 + q].x, ring[slot][mt * 4 + q].y, 0x5410);
                    al[mt][q] = prmt_(ring[slot][mt * 4 + q].x, ring[slot][mt * 4 + q].y, 0x7632);
                }
            if (ks + 2 < 8) {
                int kb = kbase + (ks + 2) * 16 + tq * 2;
                #pragma unroll
                for (int mt = 0; mt < 2; mt++) {
                    ring[slot][mt * 4 + 0] = *(const uint2*)(Hs + rows4[mt][0] * Dh + kb);
                    ring[slot][mt * 4 + 1] = *(const uint2*)(Hs + rows4[mt][1] * Dh + kb);
                    ring[slot][mt * 4 + 2] = *(const uint2*)(Hs + rows4[mt][0] * Dh + kb + 8);
                    ring[slot][mt * 4 + 3] = *(const uint2*)(Hs + rows4[mt][1] * Dh + kb + 8);
                }
            }
            int gks = wk * 8 + ks;
            uint4 bv[7];
            #pragma unroll
            for (int nt = 0; nt < 7; nt++)
                bv[nt] = *(const uint4*)(sB + (size_t)((gks * 7 + nt) * 32 + lane) * 4);
            // pass-outer, mt-outer: 14 independent accs between dependent MMAs
            #pragma unroll
            for (int mt = 0; mt < 2; mt++)
                #pragma unroll
                for (int nt = 0; nt < 7; nt++)
                    MMA_BF16(acc[mt][nt], ah[mt], bv[nt].x, bv[nt].y);
            #pragma unroll
            for (int mt = 0; mt < 2; mt++)
                #pragma unroll
                for (int nt = 0; nt < 7; nt++)
                    MMA_BF16(acc[mt][nt], al[mt], bv[nt].x, bv[nt].y);
            #pragma unroll
            for (int mt = 0; mt < 2; mt++)
                #pragma unroll
                for (int nt = 0; nt < 7; nt++)
                    MMA_BF16(acc[mt][nt], ah[mt], bv[nt].z, bv[nt].w);
        }

        if (wk != 0) {
            float* rp = sRed + (size_t)(((wk - 1) * 64) + wm * 32 + lane) * RED_STRIDE;
            #pragma unroll
            for (int mt = 0; mt < 2; mt++)
                #pragma unroll
                for (int nt = 0; nt < 7; nt++)
                    *(float4*)(rp + (mt * 7 + nt) * 4) =
                        make_float4(acc[mt][nt][0], acc[mt][nt][1], acc[mt][nt][2], acc[mt][nt][3]);
            #pragma unroll
            for (int mt = 0; mt < 2; mt++)
                #pragma unroll
                for (int nt = 0; nt < 7; nt++)
                    #pragma unroll
                    for (int ci = 0; ci < 4; ci++) acc[mt][nt][ci] = 0.0f;
        }
        __syncthreads();                     // sRed visible

        if (wk == 0) {
            #pragma unroll
            for (int q = 0; q < 3; q++) {
                const float4* rp = (const float4*)(sRed + (size_t)(q * 64 + wm * 32 + lane) * RED_STRIDE);
                #pragma unroll
                for (int mt = 0; mt < 2; mt++)
                    #pragma unroll
                    for (int nt = 0; nt < 7; nt++) {
                        float4 r = rp[mt * 7 + nt];
                        acc[mt][nt][0] += r.x; acc[mt][nt][1] += r.y;
                        acc[mt][nt][2] += r.z; acc[mt][nt][3] += r.w;
                    }
            }
            // ---- epilogue: gates + state for 4 rows x 2 d ----
            #pragma unroll
            for (int mt = 0; mt < 2; mt++)
                #pragma unroll
                for (int rh = 0; rh < 2; rh++) {
                    int b = rows4[mt][rh];
                    int len = lenr[mt][rh];
                    float dtv = 0.0f;
                    if (t + 1 < Lseq) dtv = ((t + 1) < len) ? dt[b * Lseq + t + 1] : 0.0f;
                    float hn[2];
                    uint32_t hp[2];
                    #pragma unroll
                    for (int cj = 0; cj < 2; cj++) {
                        int ci = rh * 2 + cj;
                        float i_g  = sigf(acc[mt][0][ci]);
                        float f_g  = sigf(acc[mt][1][ci]);
                        float ie_g = sigf(acc[mt][2][ci]);
                        float fe_g = sigf(acc[mt][3][ci]);
                        float o_n  = sigf(acc[mt][4][ci]);
                        float z    = tanhf(acc[mt][5][ci]);
                        float d_n  = softplusf(acc[mt][6][ci]);
                        float cs_n = f_g * stC[mt][rh][cj] + i_g * z;
                        float ce_n = fe_g * stCe[mt][rh][cj] + ie_g * z;
                        if (t == len - 1) {
                            float* f = out_final + (size_t)b * 4 * Dh + d0 + cj;
                            f[0 * Dh] = o_n;
                            f[1 * Dh] = cs_n;
                            f[2 * Dh] = ce_n;
                            f[3 * Dh] = d_n;
                        }
                        float cn = ce_n + (cs_n - ce_n) * expf(-d_n * dtv);
                        float h = o_n * tanhf(cn);
                        stC[mt][rh][cj] = cn;
                        stCe[mt][rh][cj] = ce_n;
                        hn[cj] = h;
                        hp[cj] = pack_hl(h);
                    }
                    if (t + 1 < Lseq) {
                        *(float2*)&out_h[((size_t)b * Lseq + (t + 1)) * Dh + d0] =
                            make_float2(hn[0], hn[1]);
                        *(uint2*)&g_Hsplit[(t + 1) & 1][b * Dh + d0] = make_uint2(hp[0], hp[1]);
                    }
                }
            if (t + 1 < Lseq) {
                // prefetch XP[t+1] into acc (hidden behind barrier wait)
                const float* xpt = g_xp + (size_t)(t + 1) * Bsz * ND;
                #pragma unroll
                for (int mt = 0; mt < 2; mt++)
                    #pragma unroll
                    for (int nt = 0; nt < 7; nt++) {
                        float2 x0 = *(const float2*)(xpt + (size_t)rows4[mt][0] * ND + nt * Dh + d0);
                        float2 x1 = *(const float2*)(xpt + (size_t)rows4[mt][1] * ND + nt * Dh + d0);
                        acc[mt][nt][0] = x0.x; acc[mt][nt][1] = x0.y;
                        acc[mt][nt][2] = x1.x; acc[mt][nt][3] = x1.y;
                    }
                __syncwarp();
                if (lane == 0) red_rel_add1(barp);   // publish h_{t+1}
            }
        }

        if (t + 1 < Lseq) {
            tgt += 128;
            if (tid == 0) { while (ld_acq(barp) < tgt) {} }
            __syncthreads();
        }
    }
}

// ---------------- launch ----------------
extern "C" void kernel_launch(void* const* d_in, const int* in_sizes, int n_in,
                              void* d_out, int out_size) {
    const float* x    = (const float*)d_in[0];   // (B,L,I)
    const float* dt   = (const float*)d_in[1];   // (B,L)
    const int*   sl   = (const int*)  d_in[2];   // (B,)
    const float* bos  = (const float*)d_in[3];   // (I,)
    const float* W    = (const float*)d_in[4];   // (7D, I+D)
    const float* bias = (const float*)d_in[5];   // (7D,)
    float* out = (float*)d_out;
    float* out_final = out + (size_t)Bsz * Lseq * Dh;

    cudaFuncSetAttribute(recur_kernel, cudaFuncAttributeMaxDynamicSharedMemorySize,
                         SMEM_RECUR);
    cudaFuncSetAttribute(xproj_hmma_kernel, cudaFuncAttributeMaxDynamicSharedMemorySize,
                         32768 * 4);

    prep_kernel<<<(ND + 255) / 256, 256>>>(bos, W, bias);
    pack_kernel<<<(XN + WN + 255) / 256, 256>>>(x, sl, W);
    xproj_hmma_kernel<<<dim3(28, 512), 256, 32768 * 4>>>(bias);
    recur_kernel<<<GRID_R, NTR, SMEM_RECUR>>>(W, dt, sl, out, out_final);
}

// round 8
// speedup vs baseline: 1.1064x; 1.1064x over previous
#include <cuda_runtime.h>
#include <cuda_bf16.h>
#include <math.h>
#include <stdint.h>

// Problem constants (ContTimeLSTM_66623532695635)
#define Bsz 128
#define Lseq 512
#define Iin 256
#define Dh 512
#define ND 3584          // 7*D
#define FIN 768          // I + D
#define BD (Bsz*Dh)      // 65536

#define GRID_R 128       // persistent recur blocks
#define NTR 512          // 16 warps: wm = w&3 (m16 group), wk = w>>2 (k quarter)

// ---------------- device scratch ----------------
__device__ float g_xp[(size_t)Lseq * Bsz * ND];        // ~940 MB, [t][b][n]
__device__ uint32_t g_Hsplit[2][BD];                   // packed bf16 (hi | lo<<16)
__device__ uint32_t g_xpack[(size_t)Bsz * Lseq * Iin]; // packed masked x
#define WFRAG_PLANE (28 * 16384)
__device__ uint32_t g_wfrag[2 * WFRAG_PLANE];          // W x-part fragments
__device__ float g_proj0[ND];
__device__ __align__(256) unsigned g_bar2[64];         // [0]: half 0, [32]: half 1

__device__ __forceinline__ float sigf(float x) { return 1.0f / (1.0f + expf(-x)); }
__device__ __forceinline__ float softplusf(float x) {
    return (x > 0.0f) ? (x + log1pf(expf(-x))) : log1pf(expf(x));
}
__device__ __forceinline__ unsigned ld_acq(unsigned* p) {
    unsigned v;
    asm volatile("ld.acquire.gpu.u32 %0, [%1];" : "=r"(v) : "l"(p) : "memory");
    return v;
}
__device__ __forceinline__ void red_rel_add1(unsigned* p) {
    asm volatile("red.release.gpu.global.add.u32 [%0], 1;" :: "l"(p) : "memory");
}
__device__ __forceinline__ uint32_t prmt_(uint32_t a, uint32_t b, uint32_t s) {
    uint32_t r;
    asm("prmt.b32 %0, %1, %2, %3;" : "=r"(r) : "r"(a), "r"(b), "r"(s));
    return r;
}
__device__ __forceinline__ uint32_t pack_hl(float v) {
    __nv_bfloat16 hi = __float2bfloat16(v);
    __nv_bfloat16 lo = __float2bfloat16(v - __bfloat162float(hi));
    return ((uint32_t)__bfloat16_as_ushort(lo) << 16) | __bfloat16_as_ushort(hi);
}
__device__ __forceinline__ uint32_t pack2bf(__nv_bfloat16 a, __nv_bfloat16 b) {
    return ((uint32_t)__bfloat16_as_ushort(b) << 16) | __bfloat16_as_ushort(a);
}

#define MMA_BF16(d, a, b0, b1) \
    asm volatile("mma.sync.aligned.m16n8k16.row.col.f32.bf16.bf16.f32 " \
        "{%0,%1,%2,%3}, {%4,%5,%6,%7}, {%8,%9}, {%0,%1,%2,%3};" \
        : "+f"((d)[0]), "+f"((d)[1]), "+f"((d)[2]), "+f"((d)[3]) \
        : "r"((a)[0]), "r"((a)[1]), "r"((a)[2]), "r"((a)[3]), "r"(b0), "r"(b1))

// ---------------- launch 1: reset barriers + proj0 ----------------
__global__ void prep_kernel(const float* __restrict__ bos,
                            const float* __restrict__ W,
                            const float* __restrict__ bias) {
    int n = blockIdx.x * blockDim.x + threadIdx.x;
    if (n == 0) { g_bar2[0] = 0u; g_bar2[32] = 0u; }
    if (n >= ND) return;
    const float* wrow = W + (size_t)n * FIN;
    float acc = bias[n];
    #pragma unroll 8
    for (int i = 0; i < Iin; i++) acc += bos[i] * wrow[i];
    g_proj0[n] = acc;
}

// ---------------- launch 2: pack x (masked) + W x-part fragments ----------------
#define XN (Bsz * Lseq * Iin)          // 16,777,216
#define WN (28 * 16 * 16 * 32)         // 229,376
__global__ void pack_kernel(const float* __restrict__ x,
                            const int* __restrict__ sl,
                            const float* __restrict__ W) {
    int idx = blockIdx.x * blockDim.x + threadIdx.x;
    if (idx < XN) {
        int row = idx >> 8;
        int i = idx & 255;
        int t = row >> 7;
        int b = row & 127;
        float v = (t < __ldg(sl + b)) ? x[((size_t)b * Lseq + t) * Iin + i] : 0.0f;
        g_xpack[idx] = pack_hl(v);
        return;
    }
    int e = idx - XN;
    if (e >= WN) return;
    int lane = e & 31;
    int nt = (e >> 5) & 15;
    int ks = (e >> 9) & 15;
    int nb = e >> 13;
    int gg = lane >> 2, tt = lane & 3;
    int n = nb * 128 + nt * 8 + gg;
    const float* wr = W + (size_t)n * FIN + ks * 16 + tt * 2;
    float w0 = wr[0], w1 = wr[1], w2 = wr[8], w3 = wr[9];
    __nv_bfloat16 h0 = __float2bfloat16(w0), h1 = __float2bfloat16(w1);
    __nv_bfloat16 h2 = __float2bfloat16(w2), h3 = __float2bfloat16(w3);
    __nv_bfloat16 l0 = __float2bfloat16(w0 - __bfloat162float(h0));
    __nv_bfloat16 l1 = __float2bfloat16(w1 - __bfloat162float(h1));
    __nv_bfloat16 l2 = __float2bfloat16(w2 - __bfloat162float(h2));
    __nv_bfloat16 l3 = __float2bfloat16(w3 - __bfloat162float(h3));
    size_t base = (size_t)e * 2;
    g_wfrag[base] = pack2bf(h0, h1);
    g_wfrag[base + 1] = pack2bf(h2, h3);
    g_wfrag[WFRAG_PLANE + base] = pack2bf(l0, l1);
    g_wfrag[WFRAG_PLANE + base + 1] = pack2bf(l2, l3);
}

// ---------------- launch 3: XP = mask(x) @ Wx^T + bias via HMMA ----------------
__global__ __launch_bounds__(256, 1)
void xproj_hmma_kernel(const float* __restrict__ bias) {
    extern __shared__ uint32_t sW[];   // 32768 u32
    const int tid = threadIdx.x;
    const int w = tid >> 5, lane = tid & 31;
    const int g = lane >> 2, tq = lane & 3;
    const int nb = blockIdx.x, mb = blockIdx.y;

    #pragma unroll
    for (int p = 0; p < 2; p++) {
        const uint4* src = (const uint4*)(g_wfrag + (size_t)p * WFRAG_PLANE + nb * 16384);
        uint4* dst = (uint4*)(sW + p * 16384);
        #pragma unroll
        for (int i = 0; i < 16; i++) dst[tid + i * 256] = src[tid + i * 256];
    }
    __syncthreads();

    const int r0 = mb * 128 + w * 16 + g;

    float acc[16][4];
    #pragma unroll
    for (int nt = 0; nt < 16; nt++) {
        int n = nb * 128 + nt * 8 + tq * 2;
        float b0 = __ldg(bias + n), b1 = __ldg(bias + n + 1);
        acc[nt][0] = b0; acc[nt][1] = b1; acc[nt][2] = b0; acc[nt][3] = b1;
    }

    uint2 ring[2][4];
    #pragma unroll
    for (int p = 0; p < 2; p++) {
        int kb = p * 16 + tq * 2;
        ring[p][0] = *(const uint2*)(g_xpack + (size_t)r0 * Iin + kb);
        ring[p][1] = *(const uint2*)(g_xpack + (size_t)(r0 + 8) * Iin + kb);
        ring[p][2] = *(const uint2*)(g_xpack + (size_t)r0 * Iin + kb + 8);
        ring[p][3] = *(const uint2*)(g_xpack + (size_t)(r0 + 8) * Iin + kb + 8);
    }

    #pragma unroll 2
    for (int ks = 0; ks < 16; ks++) {
        int slot = ks & 1;
        uint32_t ah[4], al[4];
        #pragma unroll
        for (int q = 0; q < 4; q++) {
            ah[q] = prmt_(ring[slot][q].x, ring[slot][q].y, 0x5410);
            al[q] = prmt_(ring[slot][q].x, ring[slot][q].y, 0x7632);
        }
        if (ks + 2 < 16) {
            int kb = (ks + 2) * 16 + tq * 2;
            ring[slot][0] = *(const uint2*)(g_xpack + (size_t)r0 * Iin + kb);
            ring[slot][1] = *(const uint2*)(g_xpack + (size_t)(r0 + 8) * Iin + kb);
            ring[slot][2] = *(const uint2*)(g_xpack + (size_t)r0 * Iin + kb + 8);
            ring[slot][3] = *(const uint2*)(g_xpack + (size_t)(r0 + 8) * Iin + kb + 8);
        }
        uint32_t bhx[16][2];
        #pragma unroll
        for (int nt = 0; nt < 16; nt++) {
            uint2 vh = *(const uint2*)(sW + ((ks * 16 + nt) * 32 + lane) * 2);
            bhx[nt][0] = vh.x; bhx[nt][1] = vh.y;
            MMA_BF16(acc[nt], ah, vh.x, vh.y);
        }
        #pragma unroll
        for (int nt = 0; nt < 16; nt++)
            MMA_BF16(acc[nt], al, bhx[nt][0], bhx[nt][1]);
        #pragma unroll
        for (int nt = 0; nt < 16; nt++) {
            uint2 vl = *(const uint2*)(sW + 16384 + ((ks * 16 + nt) * 32 + lane) * 2);
            MMA_BF16(acc[nt], ah, vl.x, vl.y);
        }
    }

    #pragma unroll
    for (int nt = 0; nt < 16; nt++) {
        int n = nb * 128 + nt * 8 + tq * 2;
        *(float2*)&g_xp[(size_t)r0 * ND + n] = make_float2(acc[nt][0], acc[nt][1]);
        *(float2*)&g_xp[(size_t)(r0 + 8) * ND + n] = make_float2(acc[nt][2], acc[nt][3]);
    }
}

// ================= launch 4: persistent recurrence =================
// 128 blocks = 64 d-chunks x 2 batch-halves. 16 warps = 4 wm (m16) x 4 wk (K=128).
// 4 warps/SMSP for latency hiding. Per-half grid barrier; tid0-only poll.
#define NFRAG 224                    // 32 ks * 7 nt
#define SB_U32 (NFRAG * 32 * 4)      // 28672 u32 = 114688 B
#define RED_STRIDE 28                // floats per (wk,wm,lane) slot
#define SRED_FLOATS (3 * 128 * RED_STRIDE)
#define SMEM_RECUR (SB_U32 * 4 + SRED_FLOATS * 4)

__global__ __launch_bounds__(NTR, 1)
void recur_kernel(const float* __restrict__ W,
                  const float* __restrict__ dt,
                  const int* __restrict__ sl,
                  float* __restrict__ out_h,
                  float* __restrict__ out_final) {
    extern __shared__ uint32_t sB[];
    float* sRed = (float*)(sB + SB_U32);

    const int tid = threadIdx.x;
    const int w = tid >> 5;
    const int lane = tid & 31;
    const int g = lane >> 2;
    const int tq = lane & 3;
    const int wm = w & 3;            // m16 group (0..3)
    const int wk = w >> 2;           // k quarter (0..3)
    const int dn = blockIdx.x >> 1;
    const int bh = blockIdx.x & 1;
    const int d0 = dn * 8 + tq * 2;
    unsigned* barp = &g_bar2[bh * 32];

    // ---- pack W h-part fragments (interleaved hi/lo) ----
    for (int e = tid; e < NFRAG * 32; e += NTR) {
        int f = e >> 5;
        int l = e & 31;
        int ks = f / 7, nt = f % 7;
        int gg = l >> 2, tt = l & 3;
        int n = nt * Dh + dn * 8 + gg;
        const float* wr = W + (size_t)n * FIN + Iin + ks * 16;
        float w0 = wr[tt * 2], w1 = wr[tt * 2 + 1];
        float w2 = wr[tt * 2 + 8], w3 = wr[tt * 2 + 9];
        __nv_bfloat16 h0 = __float2bfloat16(w0), h1 = __float2bfloat16(w1);
        __nv_bfloat16 h2 = __float2bfloat16(w2), h3 = __float2bfloat16(w3);
        __nv_bfloat16 l0 = __float2bfloat16(w0 - __bfloat162float(h0));
        __nv_bfloat16 l1 = __float2bfloat16(w1 - __bfloat162float(h1));
        __nv_bfloat16 l2 = __float2bfloat16(w2 - __bfloat162float(h2));
        __nv_bfloat16 l3 = __float2bfloat16(w3 - __bfloat162float(h3));
        uint32_t* p = sB + (size_t)e * 4;
        p[0] = pack2bf(h0, h1);
        p[1] = pack2bf(h2, h3);
        p[2] = pack2bf(l0, l1);
        p[3] = pack2bf(l2, l3);
    }

    // rows: [rh] = bh*64 + wm*16 + rh*8 + g
    int rows[2];
    rows[0] = bh * 64 + wm * 16 + g;
    rows[1] = rows[0] + 8;

    int lenr[2] = {0, 0};
    float stC[2][2], stCe[2][2];

    if (wk == 0) {
        #pragma unroll
        for (int rh = 0; rh < 2; rh++) {
            int b = rows[rh];
            lenr[rh] = sl[b];
            float dtv = dt[b * Lseq + 0];
            float h2v[2];
            uint32_t hp[2];
            #pragma unroll
            for (int cj = 0; cj < 2; cj++) {
                int d = d0 + cj;
                float p0 = g_proj0[0 * Dh + d];
                float p2 = g_proj0[2 * Dh + d];
                float p4 = g_proj0[4 * Dh + d];
                float p5 = g_proj0[5 * Dh + d];
                float p6 = g_proj0[6 * Dh + d];
                float z   = tanhf(p5);
                float cs0 = sigf(p0) * z;
                float ce0 = sigf(p2) * z;
                float o0  = sigf(p4);
                float dn0 = softplusf(p6);
                float c = ce0 + (cs0 - ce0) * expf(-dn0 * dtv);
                float h = o0 * tanhf(c);
                stC[rh][cj] = c;
                stCe[rh][cj] = ce0;
                h2v[cj] = h;
                hp[cj] = pack_hl(h);
            }
            *(float2*)&out_h[((size_t)b * Lseq + 0) * Dh + d0] = make_float2(h2v[0], h2v[1]);
            *(uint2*)&g_Hsplit[0][b * Dh + d0] = make_uint2(hp[0], hp[1]);
        }
    }

    // acc: wk0 = XP[0], others zero
    float acc[7][4];
    if (wk == 0) {
        #pragma unroll
        for (int nt = 0; nt < 7; nt++) {
            float2 x0 = *(const float2*)(g_xp + (size_t)rows[0] * ND + nt * Dh + d0);
            float2 x1 = *(const float2*)(g_xp + (size_t)rows[1] * ND + nt * Dh + d0);
            acc[nt][0] = x0.x; acc[nt][1] = x0.y;
            acc[nt][2] = x1.x; acc[nt][3] = x1.y;
        }
    } else {
        #pragma unroll
        for (int nt = 0; nt < 7; nt++)
            #pragma unroll
            for (int ci = 0; ci < 4; ci++) acc[nt][ci] = 0.0f;
    }

    __syncthreads();                         // sB + h0 stores ordered (cta fence)
    if (wk == 0 && lane == 0) red_rel_add1(barp);   // 4 arrivals/block -> 256/half

    unsigned tgt = 256;
    if (tid == 0) { while (ld_acq(barp) < tgt) {} }
    __syncthreads();

    const int kbase = wk * 128;              // u32 (d) offset of this k-quarter

    for (int t = 0; t < Lseq; t++) {
        const uint32_t* Hs = g_Hsplit[t & 1];

        // ring-2 A prefetch
        uint2 ring[2][4];
        #pragma unroll
        for (int p = 0; p < 2; p++) {
            int kb = kbase + p * 16 + tq * 2;
            ring[p][0] = *(const uint2*)(Hs + rows[0] * Dh + kb);
            ring[p][1] = *(const uint2*)(Hs + rows[1] * Dh + kb);
            ring[p][2] = *(const uint2*)(Hs + rows[0] * Dh + kb + 8);
            ring[p][3] = *(const uint2*)(Hs + rows[1] * Dh + kb + 8);
        }

        #pragma unroll 2
        for (int ks = 0; ks < 8; ks++) {
            int slot = ks & 1;
            uint32_t ah[4], al[4];
            #pragma unroll
            for (int q = 0; q < 4; q++) {
                ah[q] = prmt_(ring[slot][q].x, ring[slot][q].y, 0x5410);
                al[q] = prmt_(ring[slot][q].x, ring[slot][q].y, 0x7632);
            }
            if (ks + 2 < 8) {
                int kb = kbase + (ks + 2) * 16 + tq * 2;
                ring[slot][0] = *(const uint2*)(Hs + rows[0] * Dh + kb);
                ring[slot][1] = *(const uint2*)(Hs + rows[1] * Dh + kb);
                ring[slot][2] = *(const uint2*)(Hs + rows[0] * Dh + kb + 8);
                ring[slot][3] = *(const uint2*)(Hs + rows[1] * Dh + kb + 8);
            }
            int gks = wk * 8 + ks;
            uint4 bv[7];
            #pragma unroll
            for (int nt = 0; nt < 7; nt++)
                bv[nt] = *(const uint4*)(sB + (size_t)((gks * 7 + nt) * 32 + lane) * 4);
            // pass-outer: 7 independent accs between dependent MMAs
            #pragma unroll
            for (int nt = 0; nt < 7; nt++)
                MMA_BF16(acc[nt], ah, bv[nt].x, bv[nt].y);
            #pragma unroll
            for (int nt = 0; nt < 7; nt++)
                MMA_BF16(acc[nt], al, bv[nt].x, bv[nt].y);
            #pragma unroll
            for (int nt = 0; nt < 7; nt++)
                MMA_BF16(acc[nt], ah, bv[nt].z, bv[nt].w);
        }

        if (wk != 0) {
            float* rp = sRed + (size_t)(((wk - 1) * 128) + wm * 32 + lane) * RED_STRIDE;
            #pragma unroll
            for (int nt = 0; nt < 7; nt++)
                *(float4*)(rp + nt * 4) =
                    make_float4(acc[nt][0], acc[nt][1], acc[nt][2], acc[nt][3]);
            #pragma unroll
            for (int nt = 0; nt < 7; nt++)
                #pragma unroll
                for (int ci = 0; ci < 4; ci++) acc[nt][ci] = 0.0f;
        }
        __syncthreads();                     // sRed visible

        if (wk == 0) {
            #pragma unroll
            for (int q = 0; q < 3; q++) {
                const float4* rp = (const float4*)(sRed + (size_t)(q * 128 + wm * 32 + lane) * RED_STRIDE);
                #pragma unroll
                for (int nt = 0; nt < 7; nt++) {
                    float4 r = rp[nt];
                    acc[nt][0] += r.x; acc[nt][1] += r.y;
                    acc[nt][2] += r.z; acc[nt][3] += r.w;
                }
            }
            // ---- epilogue: gates + state for 2 rows x 2 d ----
            #pragma unroll
            for (int rh = 0; rh < 2; rh++) {
                int b = rows[rh];
                int len = lenr[rh];
                float dtv = 0.0f;
                if (t + 1 < Lseq) dtv = ((t + 1) < len) ? dt[b * Lseq + t + 1] : 0.0f;
                float hn[2];
                uint32_t hp[2];
                #pragma unroll
                for (int cj = 0; cj < 2; cj++) {
                    int ci = rh * 2 + cj;
                    float i_g  = sigf(acc[0][ci]);
                    float f_g  = sigf(acc[1][ci]);
                    float ie_g = sigf(acc[2][ci]);
                    float fe_g = sigf(acc[3][ci]);
                    float o_n  = sigf(acc[4][ci]);
                    float z    = tanhf(acc[5][ci]);
                    float d_n  = softplusf(acc[6][ci]);
                    float cs_n = f_g * stC[rh][cj] + i_g * z;
                    float ce_n = fe_g * stCe[rh][cj] + ie_g * z;
                    if (t == len - 1) {
                        float* f = out_final + (size_t)b * 4 * Dh + d0 + cj;
                        f[0 * Dh] = o_n;
                        f[1 * Dh] = cs_n;
                        f[2 * Dh] = ce_n;
                        f[3 * Dh] = d_n;
                    }
                    float cn = ce_n + (cs_n - ce_n) * expf(-d_n * dtv);
                    float h = o_n * tanhf(cn);
                    stC[rh][cj] = cn;
                    stCe[rh][cj] = ce_n;
                    hn[cj] = h;
                    hp[cj] = pack_hl(h);
                }
                if (t + 1 < Lseq) {
                    *(float2*)&out_h[((size_t)b * Lseq + (t + 1)) * Dh + d0] =
                        make_float2(hn[0], hn[1]);
                    *(uint2*)&g_Hsplit[(t + 1) & 1][b * Dh + d0] = make_uint2(hp[0], hp[1]);
                }
            }
            if (t + 1 < Lseq) {
                // prefetch XP[t+1] into acc (hidden behind barrier wait)
                const float* xpt = g_xp + (size_t)(t + 1) * Bsz * ND;
                #pragma unroll
                for (int nt = 0; nt < 7; nt++) {
                    float2 x0 = *(const float2*)(xpt + (size_t)rows[0] * ND + nt * Dh + d0);
                    float2 x1 = *(const float2*)(xpt + (size_t)rows[1] * ND + nt * Dh + d0);
                    acc[nt][0] = x0.x; acc[nt][1] = x0.y;
                    acc[nt][2] = x1.x; acc[nt][3] = x1.y;
                }
                __syncwarp();
                if (lane == 0) red_rel_add1(barp);   // publish h_{t+1}
            }
        }

        if (t + 1 < Lseq) {
            tgt += 256;
            if (tid == 0) { while (ld_acq(barp) < tgt) {} }
            __syncthreads();
        }
    }
}

// ---------------- launch ----------------
extern "C" void kernel_launch(void* const* d_in, const int* in_sizes, int n_in,
                              void* d_out, int out_size) {
    const float* x    = (const float*)d_in[0];   // (B,L,I)
    const float* dt   = (const float*)d_in[1];   // (B,L)
    const int*   sl   = (const int*)  d_in[2];   // (B,)
    const float* bos  = (const float*)d_in[3];   // (I,)
    const float* W    = (const float*)d_in[4];   // (7D, I+D)
    const float* bias = (const float*)d_in[5];   // (7D,)
    float* out = (float*)d_out;
    float* out_final = out + (size_t)Bsz * Lseq * Dh;

    cudaFuncSetAttribute(recur_kernel, cudaFuncAttributeMaxDynamicSharedMemorySize,
                         SMEM_RECUR);
    cudaFuncSetAttribute(xproj_hmma_kernel, cudaFuncAttributeMaxDynamicSharedMemorySize,
                         32768 * 4);

    prep_kernel<<<(ND + 255) / 256, 256>>>(bos, W, bias);
    pack_kernel<<<(XN + WN + 255) / 256, 256>>>(x, sl, W);
    xproj_hmma_kernel<<<dim3(28, 512), 256, 32768 * 4>>>(bias);
    recur_kernel<<<GRID_R, NTR, SMEM_RECUR>>>(W, dt, sl, out, out_final);
}